// round 1
// baseline (speedup 1.0000x reference)
#include <cuda_runtime.h>
#include <math.h>

#define NA 10000
#define NE 320000
#define F  128
#define F3 (3*F)
#define NRBF 20
#define TT 3

// ---------------- scratch (static device globals; no allocation) -------------
__device__ float g_q[NA*F];
__device__ float g_mu[NA*F3];
__device__ float g_dmu[NA*F3];
__device__ float g_E[NA*3];
__device__ float g_x[NA*F3];
__device__ float g_phi[NE*NRBF];   // phi * fcut, folded
__device__ float g_dir[NE*3];
__device__ float g_fcut[NE];
__device__ int   g_cnt[NA];
__device__ int   g_starts[NA+1];
__device__ int   g_cursor[NA];
__device__ int   g_perm[NE];

__device__ __forceinline__ float silu_f(float v) {
    return v * (1.0f / (1.0f + __expf(-v)));
}

// ---------------- init: q = emb[z], mu = 0, E per atom ----------------------
__global__ void k_init(const int* __restrict__ zn, const int* __restrict__ idx_m,
                       const float* __restrict__ e_field, const float* __restrict__ emb,
                       int n) {
    int i = blockIdx.x;
    int f = threadIdx.x;
    if (i >= n) return;
    int z = zn[i];
    g_q[i*F + f] = emb[z*F + f];
    g_mu[i*F3 + f]       = 0.0f;
    g_mu[i*F3 + F + f]   = 0.0f;
    g_mu[i*F3 + 2*F + f] = 0.0f;
    if (f < 3) g_E[i*3 + f] = e_field[idx_m[i]*3 + f];
}

// ---------------- edge precompute: d, dir, fcut, phi*fcut -------------------
__global__ void k_edge(const float* __restrict__ r_ij, int ne) {
    int e = blockIdx.x * blockDim.x + threadIdx.x;
    if (e >= ne) return;
    float x0 = r_ij[e*3+0], x1 = r_ij[e*3+1], x2 = r_ij[e*3+2];
    float d = sqrtf(x0*x0 + x1*x1 + x2*x2);
    float inv = 1.0f / d;
    g_dir[e*3+0] = x0*inv;
    g_dir[e*3+1] = x1*inv;
    g_dir[e*3+2] = x2*inv;
    float fc = (d < 5.0f) ? 0.5f * (__cosf(d * 0.6283185307179586f) + 1.0f) : 0.0f;
    g_fcut[e] = fc;
    const float w    = 5.0f / 19.0f;
    const float invw = 19.0f / 5.0f;
    float ph[NRBF];
#pragma unroll
    for (int r = 0; r < NRBF; r++) {
        float t = (d - w * (float)r) * invw;
        ph[r] = __expf(-0.5f * t * t) * fc;
    }
    float4* dst = (float4*)(g_phi + (size_t)e * NRBF);
#pragma unroll
    for (int v = 0; v < 5; v++)
        dst[v] = make_float4(ph[4*v], ph[4*v+1], ph[4*v+2], ph[4*v+3]);
}

// ---------------- counting sort of edges by idx_i ---------------------------
__global__ void k_zero(int n) {
    int i = blockIdx.x * blockDim.x + threadIdx.x;
    if (i < n) g_cnt[i] = 0;
}
__global__ void k_hist(const int* __restrict__ idx_i, int ne) {
    int e = blockIdx.x * blockDim.x + threadIdx.x;
    if (e < ne) atomicAdd(&g_cnt[idx_i[e]], 1);
}
__global__ void k_scan(int n) {
    __shared__ int ss[1024];
    int tid = threadIdx.x;
    int chunk = (n + 1023) >> 10;
    int beg = tid * chunk;
    int end = min(beg + chunk, n);
    int s = 0;
    for (int i = beg; i < end; i++) s += g_cnt[i];
    ss[tid] = s;
    __syncthreads();
    for (int off = 1; off < 1024; off <<= 1) {
        int v = (tid >= off) ? ss[tid - off] : 0;
        __syncthreads();
        ss[tid] += v;
        __syncthreads();
    }
    int base = (tid == 0) ? 0 : ss[tid - 1];
    for (int i = beg; i < end; i++) {
        g_starts[i] = base;
        g_cursor[i] = base;
        base += g_cnt[i];
    }
    if (tid == 1023) g_starts[n] = ss[1023];
}
__global__ void k_scatter(const int* __restrict__ idx_i, int ne) {
    int e = blockIdx.x * blockDim.x + threadIdx.x;
    if (e < ne) {
        int p = atomicAdd(&g_cursor[idx_i[e]], 1);
        g_perm[p] = e;
    }
}

// ---------------- inter: x = silu(q@W1+b1)@W2+b2 ---------------------------
__global__ void k_inter(const float* __restrict__ W1, const float* __restrict__ b1,
                        const float* __restrict__ W2, const float* __restrict__ b2,
                        int n) {
    __shared__ float qs[4][F];
    __shared__ float hs[4][F];
    int f = threadIdx.x;
    int a0 = blockIdx.x * 4;
#pragma unroll
    for (int a = 0; a < 4; a++) {
        int at = a0 + a;
        int atc = (at < n) ? at : 0;
        qs[a][f] = g_q[atc*F + f];
    }
    __syncthreads();
    float acc[4];
    float bb = b1[f];
#pragma unroll
    for (int a = 0; a < 4; a++) acc[a] = bb;
    for (int k = 0; k < F; k++) {
        float w = W1[k*F + f];
#pragma unroll
        for (int a = 0; a < 4; a++) acc[a] = fmaf(qs[a][k], w, acc[a]);
    }
#pragma unroll
    for (int a = 0; a < 4; a++) hs[a][f] = silu_f(acc[a]);
    __syncthreads();
    float o0[4], o1[4], o2[4];
    float c0 = b2[f], c1 = b2[F + f], c2 = b2[2*F + f];
#pragma unroll
    for (int a = 0; a < 4; a++) { o0[a] = c0; o1[a] = c1; o2[a] = c2; }
    for (int k = 0; k < F; k++) {
        float w0 = W2[k*F3 + f];
        float w1 = W2[k*F3 + F + f];
        float w2 = W2[k*F3 + 2*F + f];
#pragma unroll
        for (int a = 0; a < 4; a++) {
            float h = hs[a][k];
            o0[a] = fmaf(h, w0, o0[a]);
            o1[a] = fmaf(h, w1, o1[a]);
            o2[a] = fmaf(h, w2, o2[a]);
        }
    }
#pragma unroll
    for (int a = 0; a < 4; a++) {
        int at = a0 + a;
        if (at < n) {
            g_x[at*F3 + f]       = o0[a];
            g_x[at*F3 + F + f]   = o1[a];
            g_x[at*F3 + 2*F + f] = o2[a];
        }
    }
}

// ---------------- message passing (one block per destination atom) ---------
__global__ void k_msg(const float* __restrict__ filt_W, const float* __restrict__ filt_b,
                      const int* __restrict__ idx_j, int t, int n) {
    __shared__ float Wsm[NRBF * F3];         // 30 KB: filter weight slice for this t
    __shared__ int   se[128], sj[128];
    __shared__ float sfc[128], sd0[128], sd1[128], sd2[128];
    int i = blockIdx.x;
    int f = threadIdx.x;
    for (int idx = f; idx < NRBF * F3; idx += 128) {
        int r = idx / F3, c = idx % F3;
        Wsm[idx] = filt_W[r * (TT * F3) + t * F3 + c];
    }
    float bq = filt_b[t*F3 + f];
    float bR = filt_b[t*F3 + F + f];
    float bM = filt_b[t*F3 + 2*F + f];
    __syncthreads();
    if (i >= n) return;
    int nb = g_starts[i], nend = g_starts[i+1];
    float dq = 0.0f, dm0 = 0.0f, dm1 = 0.0f, dm2 = 0.0f;
    for (int base = nb; base < nend; base += 128) {
        int cnt = min(128, nend - base);
        __syncthreads();
        if (f < cnt) {
            int e = g_perm[base + f];
            se[f]  = e;
            sj[f]  = idx_j[e];
            sfc[f] = g_fcut[e];
            sd0[f] = g_dir[e*3+0];
            sd1[f] = g_dir[e*3+1];
            sd2[f] = g_dir[e*3+2];
        }
        __syncthreads();
        for (int k = 0; k < cnt; k++) {
            int e = se[k], j = sj[k];
            const float* xr = g_x  + (size_t)j * F3;
            const float* mr = g_mu + (size_t)j * F3;
            float xq = xr[f], xR = xr[F + f], xM = xr[2*F + f];
            float m0 = mr[f], m1 = mr[F + f], m2 = mr[2*F + f];
            float fc = sfc[k];
            float fq = bq * fc, fR = bR * fc, fM = bM * fc;
            const float* pp = g_phi + (size_t)e * NRBF;
#pragma unroll
            for (int r = 0; r < NRBF; r++) {
                float p = pp[r];
                fq = fmaf(p, Wsm[r*F3 + f],        fq);
                fR = fmaf(p, Wsm[r*F3 + F + f],    fR);
                fM = fmaf(p, Wsm[r*F3 + 2*F + f],  fM);
            }
            dq = fmaf(fq, xq, dq);
            float dR = fR * xR;
            float dM = fM * xM;
            dm0 = fmaf(dR, sd0[k], fmaf(dM, m0, dm0));
            dm1 = fmaf(dR, sd1[k], fmaf(dM, m1, dm1));
            dm2 = fmaf(dR, sd2[k], fmaf(dM, m2, dm2));
        }
    }
    g_q[i*F + f] += dq;
    g_dmu[i*F3 + f]       = dm0;
    g_dmu[i*F3 + F + f]   = dm1;
    g_dmu[i*F3 + 2*F + f] = dm2;
}

// ---------------- field interaction (also folds in dmu from message) -------
__global__ void k_field(const float* __restrict__ sW1, const float* __restrict__ sb1,
                        const float* __restrict__ sW2, const float* __restrict__ sb2,
                        const float* __restrict__ vW, int n) {
    __shared__ float qs[4][F];
    __shared__ float hs[4][F];
    __shared__ float mus[4][3][F];
    __shared__ float Es[4][3];
    int f = threadIdx.x;
    int a0 = blockIdx.x * 4;
#pragma unroll
    for (int a = 0; a < 4; a++) {
        int at = a0 + a;
        int atc = (at < n) ? at : 0;
        qs[a][f] = g_q[atc*F + f];
#pragma unroll
        for (int kv = 0; kv < 3; kv++)
            mus[a][kv][f] = g_mu[atc*F3 + kv*F + f] + g_dmu[atc*F3 + kv*F + f];
    }
    if (f < 12) {
        int a = f / 3, c = f % 3;
        int at = a0 + a;
        Es[a][c] = (at < n) ? g_E[at*3 + c] : 0.0f;
    }
    __syncthreads();
    // h = silu(q @ sW1 + sb1)
    float acc[4];
    float bb = sb1[f];
#pragma unroll
    for (int a = 0; a < 4; a++) acc[a] = bb;
    for (int k = 0; k < F; k++) {
        float w = sW1[k*F + f];
#pragma unroll
        for (int a = 0; a < 4; a++) acc[a] = fmaf(qs[a][k], w, acc[a]);
    }
#pragma unroll
    for (int a = 0; a < 4; a++) hs[a][f] = silu_f(acc[a]);
    __syncthreads();
    // a_s = h @ sW2 + sb2
    float as[4];
    float bb2 = sb2[f];
#pragma unroll
    for (int a = 0; a < 4; a++) as[a] = bb2;
    for (int k = 0; k < F; k++) {
        float w = sW2[k*F + f];
#pragma unroll
        for (int a = 0; a < 4; a++) as[a] = fmaf(hs[a][k], w, as[a]);
    }
    // a_v = mu @ vW
    float av[4][3];
#pragma unroll
    for (int a = 0; a < 4; a++)
#pragma unroll
        for (int kv = 0; kv < 3; kv++) av[a][kv] = 0.0f;
    for (int c = 0; c < F; c++) {
        float w = vW[c*F + f];
#pragma unroll
        for (int a = 0; a < 4; a++) {
#pragma unroll
            for (int kv = 0; kv < 3; kv++)
                av[a][kv] = fmaf(mus[a][kv][c], w, av[a][kv]);
        }
    }
#pragma unroll
    for (int a = 0; a < 4; a++) {
        int at = a0 + a;
        if (at >= n) continue;
        float E0 = Es[a][0], E1 = Es[a][1], E2 = Es[a][2];
        float dot = av[a][0]*E0 + av[a][1]*E1 + av[a][2]*E2;
        g_mu[at*F3 + f]       = mus[a][0][f] + as[a]*E0 - dot*av[a][0];
        g_mu[at*F3 + F + f]   = mus[a][1][f] + as[a]*E1 - dot*av[a][1];
        g_mu[at*F3 + 2*F + f] = mus[a][2][f] + as[a]*E2 - dot*av[a][2];
    }
}

// ---------------- mixing -----------------------------------------------------
__global__ void k_mix(const float* __restrict__ muW, const float* __restrict__ W1,
                      const float* __restrict__ b1,  const float* __restrict__ W2,
                      const float* __restrict__ b2,  int n) {
    __shared__ float mus[2][3][F];
    __shared__ float cs[2][2*F];
    __shared__ float hs[2][F];
    int f = threadIdx.x;
    int a0 = blockIdx.x * 2;
#pragma unroll
    for (int a = 0; a < 2; a++) {
        int at = a0 + a;
        int atc = (at < n) ? at : 0;
#pragma unroll
        for (int kv = 0; kv < 3; kv++)
            mus[a][kv][f] = g_mu[atc*F3 + kv*F + f];
    }
    __syncthreads();
    // mu_mix = mu @ muW -> V (first F cols), Wc (second F cols)
    float V[2][3], Wc[2][3];
#pragma unroll
    for (int a = 0; a < 2; a++)
#pragma unroll
        for (int kv = 0; kv < 3; kv++) { V[a][kv] = 0.0f; Wc[a][kv] = 0.0f; }
    for (int c = 0; c < F; c++) {
        float wv = muW[c*2*F + f];
        float ww = muW[c*2*F + F + f];
#pragma unroll
        for (int a = 0; a < 2; a++) {
#pragma unroll
            for (int kv = 0; kv < 3; kv++) {
                float m = mus[a][kv][c];
                V[a][kv]  = fmaf(m, wv, V[a][kv]);
                Wc[a][kv] = fmaf(m, ww, Wc[a][kv]);
            }
        }
    }
#pragma unroll
    for (int a = 0; a < 2; a++) {
        int at = a0 + a;
        int atc = (at < n) ? at : 0;
        float vn = sqrtf(V[a][0]*V[a][0] + V[a][1]*V[a][1] + V[a][2]*V[a][2] + 1e-8f);
        cs[a][f]     = g_q[atc*F + f];
        cs[a][F + f] = vn;
    }
    __syncthreads();
    // h = silu(ctx @ W1 + b1), ctx is [2F]
    float acc[2];
    float bb = b1[f];
#pragma unroll
    for (int a = 0; a < 2; a++) acc[a] = bb;
    for (int k = 0; k < 2*F; k++) {
        float w = W1[k*F + f];
#pragma unroll
        for (int a = 0; a < 2; a++) acc[a] = fmaf(cs[a][k], w, acc[a]);
    }
#pragma unroll
    for (int a = 0; a < 2; a++) hs[a][f] = silu_f(acc[a]);
    __syncthreads();
    // y = h @ W2 + b2 -> dq_i, dmu_i, dqmu_i
    float y0[2], y1[2], y2[2];
    float c0 = b2[f], c1 = b2[F + f], c2 = b2[2*F + f];
#pragma unroll
    for (int a = 0; a < 2; a++) { y0[a] = c0; y1[a] = c1; y2[a] = c2; }
    for (int k = 0; k < F; k++) {
        float w0 = W2[k*F3 + f];
        float w1 = W2[k*F3 + F + f];
        float w2 = W2[k*F3 + 2*F + f];
#pragma unroll
        for (int a = 0; a < 2; a++) {
            float h = hs[a][k];
            y0[a] = fmaf(h, w0, y0[a]);
            y1[a] = fmaf(h, w1, y1[a]);
            y2[a] = fmaf(h, w2, y2[a]);
        }
    }
#pragma unroll
    for (int a = 0; a < 2; a++) {
        int at = a0 + a;
        if (at >= n) continue;
        float sdot = V[a][0]*Wc[a][0] + V[a][1]*Wc[a][1] + V[a][2]*Wc[a][2];
        g_q[at*F + f] += y0[a] + y2[a] * sdot;
        g_mu[at*F3 + f]       = mus[a][0][f] + y1[a] * Wc[a][0];
        g_mu[at*F3 + F + f]   = mus[a][1][f] + y1[a] * Wc[a][1];
        g_mu[at*F3 + 2*F + f] = mus[a][2][f] + y1[a] * Wc[a][2];
    }
}

// ---------------- pack output [N,4,F] ---------------------------------------
__global__ void k_pack(float* __restrict__ out, int n) {
    int i = blockIdx.x;
    int f = threadIdx.x;
    if (i >= n) return;
    out[i*4*F + f] = g_q[i*F + f];
#pragma unroll
    for (int kv = 0; kv < 3; kv++)
        out[i*4*F + (1+kv)*F + f] = g_mu[i*F3 + kv*F + f];
}

// ---------------- launch -----------------------------------------------------
extern "C" void kernel_launch(void* const* d_in, const int* in_sizes, int n_in,
                              void* d_out, int out_size) {
    const int*   zn      = (const int*)  d_in[0];
    const float* r_ij    = (const float*)d_in[1];
    const int*   idx_i   = (const int*)  d_in[2];
    const int*   idx_j   = (const int*)  d_in[3];
    const int*   idx_m   = (const int*)  d_in[4];
    const float* e_field = (const float*)d_in[5];
    const float* emb     = (const float*)d_in[6];
    const float* filt_W  = (const float*)d_in[7];
    const float* filt_b  = (const float*)d_in[8];
    const float* iW1     = (const float*)d_in[9];
    const float* ib1     = (const float*)d_in[10];
    const float* iW2     = (const float*)d_in[11];
    const float* ib2     = (const float*)d_in[12];
    const float* fsW1    = (const float*)d_in[13];
    const float* fsb1    = (const float*)d_in[14];
    const float* fsW2    = (const float*)d_in[15];
    const float* fsb2    = (const float*)d_in[16];
    const float* fvW     = (const float*)d_in[17];
    const float* mmuW    = (const float*)d_in[18];
    const float* mW1     = (const float*)d_in[19];
    const float* mb1     = (const float*)d_in[20];
    const float* mW2     = (const float*)d_in[21];
    const float* mb2     = (const float*)d_in[22];

    int n  = in_sizes[0];   // 10000
    int ne = in_sizes[2];   // 320000

    k_init<<<n, F>>>(zn, idx_m, e_field, emb, n);
    k_edge<<<(ne + 255) / 256, 256>>>(r_ij, ne);
    k_zero<<<(n + 255) / 256, 256>>>(n);
    k_hist<<<(ne + 255) / 256, 256>>>(idx_i, ne);
    k_scan<<<1, 1024>>>(n);
    k_scatter<<<(ne + 255) / 256, 256>>>(idx_i, ne);

    for (int t = 0; t < TT; t++) {
        k_inter<<<(n + 3) / 4, F>>>(iW1 + t*F*F, ib1 + t*F,
                                    iW2 + t*F*F3, ib2 + t*F3, n);
        k_msg<<<n, F>>>(filt_W, filt_b, idx_j, t, n);
        k_field<<<(n + 3) / 4, F>>>(fsW1 + t*F*F, fsb1 + t*F,
                                    fsW2 + t*F*F, fsb2 + t*F,
                                    fvW + t*F*F, n);
        k_mix<<<(n + 1) / 2, F>>>(mmuW + t*F*2*F, mW1 + t*2*F*F, mb1 + t*F,
                                  mW2 + t*F*F3, mb2 + t*F3, n);
    }
    k_pack<<<n, F>>>((float*)d_out, n);
}

// round 2
// speedup vs baseline: 1.2809x; 1.2809x over previous
#include <cuda_runtime.h>
#include <math.h>

#define NA 10000
#define NE 320000
#define F  128
#define F3 (3*F)
#define NRBF 20
#define TT 3

typedef unsigned long long ull;

// ---------------- scratch (static device globals; no allocation) -------------
__device__ float g_q[NA*F];
__device__ float g_mu[NA*F3];
__device__ float g_dmu[NA*F3];
__device__ float g_E[NA*3];
__device__ float g_x[NA*F3];
__device__ float g_phi[NE*NRBF];   // phi * fcut, folded
__device__ float g_dir[NE*3];
__device__ float g_fcut[NE];
__device__ int   g_cnt[NA];
__device__ int   g_starts[NA+1];
__device__ int   g_cursor[NA];
__device__ int   g_perm[NE];

__device__ __forceinline__ float silu_f(float v) {
    return v * (1.0f / (1.0f + __expf(-v)));
}

// ---- packed f32x2 helpers (Blackwell; ptxas never emits FFMA2 from C++) ----
__device__ __forceinline__ ull pk2(float lo, float hi) {
    ull r; asm("mov.b64 %0, {%1,%2};" : "=l"(r) : "f"(lo), "f"(hi)); return r;
}
__device__ __forceinline__ void unpk2(ull v, float& lo, float& hi) {
    asm("mov.b64 {%0,%1}, %2;" : "=f"(lo), "=f"(hi) : "l"(v));
}
__device__ __forceinline__ ull ffma2(ull a, ull b, ull c) {
    ull d; asm("fma.rn.f32x2 %0, %1, %2, %3;" : "=l"(d) : "l"(a), "l"(b), "l"(c));
    return d;
}

// ---------------- init: q = emb[z], mu = 0, E per atom ----------------------
__global__ void k_init(const int* __restrict__ zn, const int* __restrict__ idx_m,
                       const float* __restrict__ e_field, const float* __restrict__ emb,
                       int n) {
    int i = blockIdx.x;
    int f = threadIdx.x;
    if (i >= n) return;
    int z = zn[i];
    g_q[i*F + f] = emb[z*F + f];
    g_mu[i*F3 + f]       = 0.0f;
    g_mu[i*F3 + F + f]   = 0.0f;
    g_mu[i*F3 + 2*F + f] = 0.0f;
    if (f < 3) g_E[i*3 + f] = e_field[idx_m[i]*3 + f];
}

// ---------------- edge precompute: d, dir, fcut, phi*fcut -------------------
__global__ void k_edge(const float* __restrict__ r_ij, int ne) {
    int e = blockIdx.x * blockDim.x + threadIdx.x;
    if (e >= ne) return;
    float x0 = r_ij[e*3+0], x1 = r_ij[e*3+1], x2 = r_ij[e*3+2];
    float d = sqrtf(x0*x0 + x1*x1 + x2*x2);
    float inv = 1.0f / d;
    g_dir[e*3+0] = x0*inv;
    g_dir[e*3+1] = x1*inv;
    g_dir[e*3+2] = x2*inv;
    float fc = (d < 5.0f) ? 0.5f * (__cosf(d * 0.6283185307179586f) + 1.0f) : 0.0f;
    g_fcut[e] = fc;
    const float w    = 5.0f / 19.0f;
    const float invw = 19.0f / 5.0f;
    float ph[NRBF];
#pragma unroll
    for (int r = 0; r < NRBF; r++) {
        float t = (d - w * (float)r) * invw;
        ph[r] = __expf(-0.5f * t * t) * fc;
    }
    float4* dst = (float4*)(g_phi + (size_t)e * NRBF);
#pragma unroll
    for (int v = 0; v < 5; v++)
        dst[v] = make_float4(ph[4*v], ph[4*v+1], ph[4*v+2], ph[4*v+3]);
}

// ---------------- counting sort of edges by idx_i ---------------------------
__global__ void k_zero(int n) {
    int i = blockIdx.x * blockDim.x + threadIdx.x;
    if (i < n) g_cnt[i] = 0;
}
__global__ void k_hist(const int* __restrict__ idx_i, int ne) {
    int e = blockIdx.x * blockDim.x + threadIdx.x;
    if (e < ne) atomicAdd(&g_cnt[idx_i[e]], 1);
}
__global__ void k_scan(int n) {
    __shared__ int ss[1024];
    int tid = threadIdx.x;
    int chunk = (n + 1023) >> 10;
    int beg = tid * chunk;
    int end = min(beg + chunk, n);
    int s = 0;
    for (int i = beg; i < end; i++) s += g_cnt[i];
    ss[tid] = s;
    __syncthreads();
    for (int off = 1; off < 1024; off <<= 1) {
        int v = (tid >= off) ? ss[tid - off] : 0;
        __syncthreads();
        ss[tid] += v;
        __syncthreads();
    }
    int base = (tid == 0) ? 0 : ss[tid - 1];
    for (int i = beg; i < end; i++) {
        g_starts[i] = base;
        g_cursor[i] = base;
        base += g_cnt[i];
    }
    if (tid == 1023) g_starts[n] = ss[1023];
}
__global__ void k_scatter(const int* __restrict__ idx_i, int ne) {
    int e = blockIdx.x * blockDim.x + threadIdx.x;
    if (e < ne) {
        int p = atomicAdd(&g_cursor[idx_i[e]], 1);
        g_perm[p] = e;
    }
}

// ---------------- inter: x = silu(q@W1+b1)@W2+b2 ---------------------------
__global__ void k_inter(const float* __restrict__ W1, const float* __restrict__ b1,
                        const float* __restrict__ W2, const float* __restrict__ b2,
                        int n) {
    __shared__ float qs[4][F];
    __shared__ float hs[4][F];
    int f = threadIdx.x;
    int a0 = blockIdx.x * 4;
#pragma unroll
    for (int a = 0; a < 4; a++) {
        int at = a0 + a;
        int atc = (at < n) ? at : 0;
        qs[a][f] = g_q[atc*F + f];
    }
    __syncthreads();
    float acc[4];
    float bb = b1[f];
#pragma unroll
    for (int a = 0; a < 4; a++) acc[a] = bb;
    for (int k = 0; k < F; k++) {
        float w = W1[k*F + f];
#pragma unroll
        for (int a = 0; a < 4; a++) acc[a] = fmaf(qs[a][k], w, acc[a]);
    }
#pragma unroll
    for (int a = 0; a < 4; a++) hs[a][f] = silu_f(acc[a]);
    __syncthreads();
    float o0[4], o1[4], o2[4];
    float c0 = b2[f], c1 = b2[F + f], c2 = b2[2*F + f];
#pragma unroll
    for (int a = 0; a < 4; a++) { o0[a] = c0; o1[a] = c1; o2[a] = c2; }
    for (int k = 0; k < F; k++) {
        float w0 = W2[k*F3 + f];
        float w1 = W2[k*F3 + F + f];
        float w2 = W2[k*F3 + 2*F + f];
#pragma unroll
        for (int a = 0; a < 4; a++) {
            float h = hs[a][k];
            o0[a] = fmaf(h, w0, o0[a]);
            o1[a] = fmaf(h, w1, o1[a]);
            o2[a] = fmaf(h, w2, o2[a]);
        }
    }
#pragma unroll
    for (int a = 0; a < 4; a++) {
        int at = a0 + a;
        if (at < n) {
            g_x[at*F3 + f]       = o0[a];
            g_x[at*F3 + F + f]   = o1[a];
            g_x[at*F3 + 2*F + f] = o2[a];
        }
    }
}

// ---------------- message passing (one block per destination atom) ---------
// Filter weights register-hoisted; phi tile staged in smem; RBF reduction
// packed pairwise over r with fma.rn.f32x2 (lanes = even-r / odd-r partials).
__global__ void __launch_bounds__(128) k_msg(
        const float* __restrict__ filt_W, const float* __restrict__ filt_b,
        const int* __restrict__ idx_j, int t, int n) {
    __shared__ float sphi[128 * NRBF];       // 10 KB, rows 80B (16B-aligned)
    __shared__ int   sj[128];
    __shared__ float sfc[128], sd0[128], sd1[128], sd2[128];
    int i = blockIdx.x;
    int f = threadIdx.x;

    // hoist this thread's 60 filter weights into packed register pairs
    ull wq2[NRBF/2], wR2[NRBF/2], wM2[NRBF/2];
#pragma unroll
    for (int m = 0; m < NRBF/2; m++) {
        const float* base = filt_W + (2*m) * (TT*F3) + t*F3;
        float aq = base[f],        bqv = base[TT*F3 + f];
        float aR = base[F + f],    bRv = base[TT*F3 + F + f];
        float aM = base[2*F + f],  bMv = base[TT*F3 + 2*F + f];
        wq2[m] = pk2(aq, bqv);
        wR2[m] = pk2(aR, bRv);
        wM2[m] = pk2(aM, bMv);
    }
    float bq = filt_b[t*F3 + f];
    float bR = filt_b[t*F3 + F + f];
    float bM = filt_b[t*F3 + 2*F + f];

    if (i >= n) return;
    int nb = g_starts[i], nend = g_starts[i+1];
    float dq = 0.0f, dm0 = 0.0f, dm1 = 0.0f, dm2 = 0.0f;

    for (int base = nb; base < nend; base += 128) {
        int cnt = min(128, nend - base);
        __syncthreads();
        if (f < cnt) {
            int e = g_perm[base + f];
            sj[f]  = idx_j[e];
            sfc[f] = g_fcut[e];
            sd0[f] = g_dir[e*3+0];
            sd1[f] = g_dir[e*3+1];
            sd2[f] = g_dir[e*3+2];
            const float4* pp = (const float4*)(g_phi + (size_t)e * NRBF);
            float4* dst = (float4*)(sphi + f * NRBF);
#pragma unroll
            for (int v = 0; v < 5; v++) dst[v] = pp[v];
        }
        __syncthreads();
        for (int k = 0; k < cnt; k++) {
            float fc = sfc[k];
            ull accq = pk2(bq * fc, 0.0f);
            ull accR = pk2(bR * fc, 0.0f);
            ull accM = pk2(bM * fc, 0.0f);
            const ull* p2 = (const ull*)(sphi + k * NRBF);
#pragma unroll
            for (int m = 0; m < NRBF/2; m++) {
                ull pp = p2[m];
                accq = ffma2(pp, wq2[m], accq);
                accR = ffma2(pp, wR2[m], accR);
                accM = ffma2(pp, wM2[m], accM);
            }
            float ql, qh, Rl, Rh, Ml, Mh;
            unpk2(accq, ql, qh);
            unpk2(accR, Rl, Rh);
            unpk2(accM, Ml, Mh);
            float fq = ql + qh, fR = Rl + Rh, fM = Ml + Mh;

            int j = sj[k];
            const float* xr = g_x  + (size_t)j * F3;
            const float* mr = g_mu + (size_t)j * F3;
            float xq = xr[f], xR = xr[F + f], xM = xr[2*F + f];
            float m0 = mr[f], m1 = mr[F + f], m2 = mr[2*F + f];

            dq = fmaf(fq, xq, dq);
            float dR = fR * xR;
            float dM = fM * xM;
            dm0 = fmaf(dR, sd0[k], fmaf(dM, m0, dm0));
            dm1 = fmaf(dR, sd1[k], fmaf(dM, m1, dm1));
            dm2 = fmaf(dR, sd2[k], fmaf(dM, m2, dm2));
        }
    }
    g_q[i*F + f] += dq;
    g_dmu[i*F3 + f]       = dm0;
    g_dmu[i*F3 + F + f]   = dm1;
    g_dmu[i*F3 + 2*F + f] = dm2;
}

// ---------------- field interaction (also folds in dmu from message) -------
__global__ void k_field(const float* __restrict__ sW1, const float* __restrict__ sb1,
                        const float* __restrict__ sW2, const float* __restrict__ sb2,
                        const float* __restrict__ vW, int n) {
    __shared__ float qs[4][F];
    __shared__ float hs[4][F];
    __shared__ float mus[4][3][F];
    __shared__ float Es[4][3];
    int f = threadIdx.x;
    int a0 = blockIdx.x * 4;
#pragma unroll
    for (int a = 0; a < 4; a++) {
        int at = a0 + a;
        int atc = (at < n) ? at : 0;
        qs[a][f] = g_q[atc*F + f];
#pragma unroll
        for (int kv = 0; kv < 3; kv++)
            mus[a][kv][f] = g_mu[atc*F3 + kv*F + f] + g_dmu[atc*F3 + kv*F + f];
    }
    if (f < 12) {
        int a = f / 3, c = f % 3;
        int at = a0 + a;
        Es[a][c] = (at < n) ? g_E[at*3 + c] : 0.0f;
    }
    __syncthreads();
    float acc[4];
    float bb = sb1[f];
#pragma unroll
    for (int a = 0; a < 4; a++) acc[a] = bb;
    for (int k = 0; k < F; k++) {
        float w = sW1[k*F + f];
#pragma unroll
        for (int a = 0; a < 4; a++) acc[a] = fmaf(qs[a][k], w, acc[a]);
    }
#pragma unroll
    for (int a = 0; a < 4; a++) hs[a][f] = silu_f(acc[a]);
    __syncthreads();
    float as[4];
    float bb2 = sb2[f];
#pragma unroll
    for (int a = 0; a < 4; a++) as[a] = bb2;
    for (int k = 0; k < F; k++) {
        float w = sW2[k*F + f];
#pragma unroll
        for (int a = 0; a < 4; a++) as[a] = fmaf(hs[a][k], w, as[a]);
    }
    float av[4][3];
#pragma unroll
    for (int a = 0; a < 4; a++)
#pragma unroll
        for (int kv = 0; kv < 3; kv++) av[a][kv] = 0.0f;
    for (int c = 0; c < F; c++) {
        float w = vW[c*F + f];
#pragma unroll
        for (int a = 0; a < 4; a++) {
#pragma unroll
            for (int kv = 0; kv < 3; kv++)
                av[a][kv] = fmaf(mus[a][kv][c], w, av[a][kv]);
        }
    }
#pragma unroll
    for (int a = 0; a < 4; a++) {
        int at = a0 + a;
        if (at >= n) continue;
        float E0 = Es[a][0], E1 = Es[a][1], E2 = Es[a][2];
        float dot = av[a][0]*E0 + av[a][1]*E1 + av[a][2]*E2;
        g_mu[at*F3 + f]       = mus[a][0][f] + as[a]*E0 - dot*av[a][0];
        g_mu[at*F3 + F + f]   = mus[a][1][f] + as[a]*E1 - dot*av[a][1];
        g_mu[at*F3 + 2*F + f] = mus[a][2][f] + as[a]*E2 - dot*av[a][2];
    }
}

// ---------------- mixing -----------------------------------------------------
__global__ void k_mix(const float* __restrict__ muW, const float* __restrict__ W1,
                      const float* __restrict__ b1,  const float* __restrict__ W2,
                      const float* __restrict__ b2,  int n) {
    __shared__ float mus[2][3][F];
    __shared__ float cs[2][2*F];
    __shared__ float hs[2][F];
    int f = threadIdx.x;
    int a0 = blockIdx.x * 2;
#pragma unroll
    for (int a = 0; a < 2; a++) {
        int at = a0 + a;
        int atc = (at < n) ? at : 0;
#pragma unroll
        for (int kv = 0; kv < 3; kv++)
            mus[a][kv][f] = g_mu[atc*F3 + kv*F + f];
    }
    __syncthreads();
    float V[2][3], Wc[2][3];
#pragma unroll
    for (int a = 0; a < 2; a++)
#pragma unroll
        for (int kv = 0; kv < 3; kv++) { V[a][kv] = 0.0f; Wc[a][kv] = 0.0f; }
    for (int c = 0; c < F; c++) {
        float wv = muW[c*2*F + f];
        float ww = muW[c*2*F + F + f];
#pragma unroll
        for (int a = 0; a < 2; a++) {
#pragma unroll
            for (int kv = 0; kv < 3; kv++) {
                float m = mus[a][kv][c];
                V[a][kv]  = fmaf(m, wv, V[a][kv]);
                Wc[a][kv] = fmaf(m, ww, Wc[a][kv]);
            }
        }
    }
#pragma unroll
    for (int a = 0; a < 2; a++) {
        int at = a0 + a;
        int atc = (at < n) ? at : 0;
        float vn = sqrtf(V[a][0]*V[a][0] + V[a][1]*V[a][1] + V[a][2]*V[a][2] + 1e-8f);
        cs[a][f]     = g_q[atc*F + f];
        cs[a][F + f] = vn;
    }
    __syncthreads();
    float acc[2];
    float bb = b1[f];
#pragma unroll
    for (int a = 0; a < 2; a++) acc[a] = bb;
    for (int k = 0; k < 2*F; k++) {
        float w = W1[k*F + f];
#pragma unroll
        for (int a = 0; a < 2; a++) acc[a] = fmaf(cs[a][k], w, acc[a]);
    }
#pragma unroll
    for (int a = 0; a < 2; a++) hs[a][f] = silu_f(acc[a]);
    __syncthreads();
    float y0[2], y1[2], y2[2];
    float c0 = b2[f], c1 = b2[F + f], c2 = b2[2*F + f];
#pragma unroll
    for (int a = 0; a < 2; a++) { y0[a] = c0; y1[a] = c1; y2[a] = c2; }
    for (int k = 0; k < F; k++) {
        float w0 = W2[k*F3 + f];
        float w1 = W2[k*F3 + F + f];
        float w2 = W2[k*F3 + 2*F + f];
#pragma unroll
        for (int a = 0; a < 2; a++) {
            float h = hs[a][k];
            y0[a] = fmaf(h, w0, y0[a]);
            y1[a] = fmaf(h, w1, y1[a]);
            y2[a] = fmaf(h, w2, y2[a]);
        }
    }
#pragma unroll
    for (int a = 0; a < 2; a++) {
        int at = a0 + a;
        if (at >= n) continue;
        float sdot = V[a][0]*Wc[a][0] + V[a][1]*Wc[a][1] + V[a][2]*Wc[a][2];
        g_q[at*F + f] += y0[a] + y2[a] * sdot;
        g_mu[at*F3 + f]       = mus[a][0][f] + y1[a] * Wc[a][0];
        g_mu[at*F3 + F + f]   = mus[a][1][f] + y1[a] * Wc[a][1];
        g_mu[at*F3 + 2*F + f] = mus[a][2][f] + y1[a] * Wc[a][2];
    }
}

// ---------------- pack output [N,4,F] ---------------------------------------
__global__ void k_pack(float* __restrict__ out, int n) {
    int i = blockIdx.x;
    int f = threadIdx.x;
    if (i >= n) return;
    out[i*4*F + f] = g_q[i*F + f];
#pragma unroll
    for (int kv = 0; kv < 3; kv++)
        out[i*4*F + (1+kv)*F + f] = g_mu[i*F3 + kv*F + f];
}

// ---------------- launch -----------------------------------------------------
extern "C" void kernel_launch(void* const* d_in, const int* in_sizes, int n_in,
                              void* d_out, int out_size) {
    const int*   zn      = (const int*)  d_in[0];
    const float* r_ij    = (const float*)d_in[1];
    const int*   idx_i   = (const int*)  d_in[2];
    const int*   idx_j   = (const int*)  d_in[3];
    const int*   idx_m   = (const int*)  d_in[4];
    const float* e_field = (const float*)d_in[5];
    const float* emb     = (const float*)d_in[6];
    const float* filt_W  = (const float*)d_in[7];
    const float* filt_b  = (const float*)d_in[8];
    const float* iW1     = (const float*)d_in[9];
    const float* ib1     = (const float*)d_in[10];
    const float* iW2     = (const float*)d_in[11];
    const float* ib2     = (const float*)d_in[12];
    const float* fsW1    = (const float*)d_in[13];
    const float* fsb1    = (const float*)d_in[14];
    const float* fsW2    = (const float*)d_in[15];
    const float* fsb2    = (const float*)d_in[16];
    const float* fvW     = (const float*)d_in[17];
    const float* mmuW    = (const float*)d_in[18];
    const float* mW1     = (const float*)d_in[19];
    const float* mb1     = (const float*)d_in[20];
    const float* mW2     = (const float*)d_in[21];
    const float* mb2     = (const float*)d_in[22];

    int n  = in_sizes[0];   // 10000
    int ne = in_sizes[2];   // 320000

    k_init<<<n, F>>>(zn, idx_m, e_field, emb, n);
    k_edge<<<(ne + 255) / 256, 256>>>(r_ij, ne);
    k_zero<<<(n + 255) / 256, 256>>>(n);
    k_hist<<<(ne + 255) / 256, 256>>>(idx_i, ne);
    k_scan<<<1, 1024>>>(n);
    k_scatter<<<(ne + 255) / 256, 256>>>(idx_i, ne);

    for (int t = 0; t < TT; t++) {
        k_inter<<<(n + 3) / 4, F>>>(iW1 + t*F*F, ib1 + t*F,
                                    iW2 + t*F*F3, ib2 + t*F3, n);
        k_msg<<<n, F>>>(filt_W, filt_b, idx_j, t, n);
        k_field<<<(n + 3) / 4, F>>>(fsW1 + t*F*F, fsb1 + t*F,
                                    fsW2 + t*F*F, fsb2 + t*F,
                                    fvW + t*F*F, n);
        k_mix<<<(n + 1) / 2, F>>>(mmuW + t*F*2*F, mW1 + t*2*F*F, mb1 + t*F,
                                  mW2 + t*F*F3, mb2 + t*F3, n);
    }
    k_pack<<<n, F>>>((float*)d_out, n);
}